// round 1
// baseline (speedup 1.0000x reference)
#include <cuda_runtime.h>
#include <cuda_bf16.h>

// Problem constants (fixed by setup_inputs)
#define Bn 32
#define Hn 384
#define Wn 384
#define Cn 8
#define Fn 7
#define NPIX (Bn*Hn*Wn)          // 4,718,592
#define NELEM (NPIX*Cn)          // 37,748,736

// Scratch (allocation-free rule: __device__ globals)
__device__ float g_qA[NELEM];
__device__ float g_qB[NELEM];
__device__ float g_u[NELEM];

// ---- packed f32x2 helpers (Blackwell FFMA2: PTX-only) ----
__device__ __forceinline__ unsigned long long pk2(float lo, float hi) {
    unsigned long long r;
    asm("mov.b64 %0,{%1,%2};" : "=l"(r) : "f"(lo), "f"(hi));
    return r;
}
__device__ __forceinline__ void upk2(unsigned long long v, float& lo, float& hi) {
    asm("mov.b64 {%0,%1},%2;" : "=f"(lo), "=f"(hi) : "l"(v));
}
__device__ __forceinline__ unsigned long long ffma2(unsigned long long a,
                                                    unsigned long long b,
                                                    unsigned long long c) {
    unsigned long long d;
    asm("fma.rn.f32x2 %0,%1,%2,%3;" : "=l"(d) : "l"(a), "l"(b), "l"(c));
    return d;
}

// ============================================================
// Kernel 1: q0 = softmax(x), u = -log(max(q0, 1e-6))
// ============================================================
__global__ void k_init(const float* __restrict__ x,
                       float* __restrict__ q,
                       float* __restrict__ u) {
    int i = blockIdx.x * blockDim.x + threadIdx.x;
    if (i >= NPIX) return;
    const float4* xp = reinterpret_cast<const float4*>(x) + (long)i * 2;
    float4 a = xp[0], b4 = xp[1];
    float v[8] = {a.x, a.y, a.z, a.w, b4.x, b4.y, b4.z, b4.w};
    float m = v[0];
#pragma unroll
    for (int c = 1; c < 8; c++) m = fmaxf(m, v[c]);
    float e[8], s = 0.f;
#pragma unroll
    for (int c = 0; c < 8; c++) { e[c] = __expf(v[c] - m); s += e[c]; }
    float inv = 1.f / s;
    float qq[8], uu[8];
#pragma unroll
    for (int c = 0; c < 8; c++) {
        qq[c] = e[c] * inv;
        uu[c] = -__logf(fmaxf(qq[c], 1e-6f));
    }
    float4* qp = reinterpret_cast<float4*>(q) + (long)i * 2;
    qp[0] = make_float4(qq[0], qq[1], qq[2], qq[3]);
    qp[1] = make_float4(qq[4], qq[5], qq[6], qq[7]);
    float4* up = reinterpret_cast<float4*>(u) + (long)i * 2;
    up[0] = make_float4(uu[0], uu[1], uu[2], uu[3]);
    up[1] = make_float4(uu[4], uu[5], uu[6], uu[7]);
}

// ============================================================
// Kernel 2: one mean-field iteration, fused:
//   penalty = conv7x7(qin, k_masked); logits = -(u+penalty)
//   logits = logits @ W + b;  q = softmax(logits)  (or emit logits)
// Tile: 64(x) x 8(y), halo 3. Block (16,8)=128 thr, 4 px/thread.
// ============================================================
#define TY 8
#define TX 64
#define HLY (TY + 6)   // 14
#define HLX (TX + 6)   // 70

__global__ __launch_bounds__(128)
void k_iter(const float* __restrict__ qin,
            const float* __restrict__ u,
            const float* __restrict__ kw,      // [7,7,8,8]
            const float* __restrict__ wsc,     // [8,8]
            const float* __restrict__ bsc,     // [8]
            float* __restrict__ qout,
            float* __restrict__ logits_out) {  // non-null on last iter
    __shared__ __align__(16) float sq[HLY][HLX][Cn];   // 31,360 B
    __shared__ __align__(16) float sk[Fn * Fn][Cn][Cn]; // 12,544 B
    __shared__ __align__(16) float sw[Cn][Cn];
    __shared__ __align__(16) float sb[Cn];

    const int tid = threadIdx.y * 16 + threadIdx.x;

    // masked kernel -> smem (zero ci==co pairs)
    for (int idx = tid; idx < Fn * Fn * Cn * Cn; idx += 128) {
        int co = idx & 7, ci = (idx >> 3) & 7;
        float v = kw[idx];
        (&sk[0][0][0])[idx] = (ci == co) ? 0.f : v;
    }
    if (tid < 64) (&sw[0][0])[tid] = wsc[tid];
    if (tid < 8) sb[tid] = bsc[tid];

    const int bx = blockIdx.x;   // 0..5
    const int by = blockIdx.y;   // 0..47
    const int bz = blockIdx.z;   // 0..31
    const int gx0 = bx * TX - 3, gy0 = by * TY - 3;
    const float* qbase = qin + (long)bz * Hn * Wn * Cn;

    // halo load (zero-padded), float4-granular, coalesced
    for (int f = tid; f < HLY * HLX * 2; f += 128) {
        int half = f & 1;
        int pix = f >> 1;
        int px = pix % HLX;
        int row = pix / HLX;
        int gy = gy0 + row, gx = gx0 + px;
        float4 v = make_float4(0.f, 0.f, 0.f, 0.f);
        if (gy >= 0 && gy < Hn && gx >= 0 && gx < Wn)
            v = *reinterpret_cast<const float4*>(qbase + ((long)gy * Wn + gx) * Cn + half * 4);
        *reinterpret_cast<float4*>(&sq[row][px][half * 4]) = v;
    }
    __syncthreads();

    const int txi = threadIdx.x, tyi = threadIdx.y;

    unsigned long long acc[4][4];
#pragma unroll
    for (int p = 0; p < 4; p++)
#pragma unroll
        for (int j = 0; j < 4; j++) acc[p][j] = pk2(0.f, 0.f);

#pragma unroll 1
    for (int dy = 0; dy < Fn; dy++) {
        const float* row0 = &sq[tyi + dy][0][0];
#pragma unroll 1
        for (int dx = 0; dx < Fn; dx++) {
            float4 qA[4], qB[4];
#pragma unroll
            for (int p = 0; p < 4; p++) {
                const float* qp = row0 + (txi + p * 16 + dx) * Cn;
                qA[p] = *reinterpret_cast<const float4*>(qp);
                qB[p] = *reinterpret_cast<const float4*>(qp + 4);
            }
            const ulonglong2* kp =
                reinterpret_cast<const ulonglong2*>(&sk[dy * Fn + dx][0][0]);
#pragma unroll
            for (int ci = 0; ci < 8; ci++) {
                ulonglong2 kA = kp[ci * 2 + 0];   // co 0..3
                ulonglong2 kB = kp[ci * 2 + 1];   // co 4..7
#pragma unroll
                for (int p = 0; p < 4; p++) {
                    float qv = (ci == 0) ? qA[p].x : (ci == 1) ? qA[p].y
                             : (ci == 2) ? qA[p].z : (ci == 3) ? qA[p].w
                             : (ci == 4) ? qB[p].x : (ci == 5) ? qB[p].y
                             : (ci == 6) ? qB[p].z : qB[p].w;
                    unsigned long long qq = pk2(qv, qv);
                    acc[p][0] = ffma2(qq, kA.x, acc[p][0]);
                    acc[p][1] = ffma2(qq, kA.y, acc[p][1]);
                    acc[p][2] = ffma2(qq, kB.x, acc[p][2]);
                    acc[p][3] = ffma2(qq, kB.y, acc[p][3]);
                }
            }
        }
    }

    // epilogue: u-add, 1x1 projection (+bias), softmax or logits emit
    const float* ub = u + (long)bz * Hn * Wn * Cn;
    float* qo = qout + (long)bz * Hn * Wn * Cn;

#pragma unroll
    for (int p = 0; p < 4; p++) {
        const int gx = bx * TX + txi + p * 16;
        const int gy = by * TY + tyi;
        const long gi = ((long)gy * Wn + gx) * Cn;
        float4 uA = *reinterpret_cast<const float4*>(ub + gi);
        float4 uB = *reinterpret_cast<const float4*>(ub + gi + 4);
        float pen[8];
        upk2(acc[p][0], pen[0], pen[1]);
        upk2(acc[p][1], pen[2], pen[3]);
        upk2(acc[p][2], pen[4], pen[5]);
        upk2(acc[p][3], pen[6], pen[7]);
        float lg[8];
        lg[0] = -(uA.x + pen[0]); lg[1] = -(uA.y + pen[1]);
        lg[2] = -(uA.z + pen[2]); lg[3] = -(uA.w + pen[3]);
        lg[4] = -(uB.x + pen[4]); lg[5] = -(uB.y + pen[5]);
        lg[6] = -(uB.z + pen[6]); lg[7] = -(uB.w + pen[7]);

        // 1x1: out[d] = sum_c lg[c]*W[c][d] + b[d]
        unsigned long long o01 = pk2(sb[0], sb[1]);
        unsigned long long o23 = pk2(sb[2], sb[3]);
        unsigned long long o45 = pk2(sb[4], sb[5]);
        unsigned long long o67 = pk2(sb[6], sb[7]);
#pragma unroll
        for (int c = 0; c < 8; c++) {
            const ulonglong2* wp = reinterpret_cast<const ulonglong2*>(&sw[c][0]);
            ulonglong2 wA = wp[0], wB = wp[1];
            unsigned long long lc = pk2(lg[c], lg[c]);
            o01 = ffma2(lc, wA.x, o01);
            o23 = ffma2(lc, wA.y, o23);
            o45 = ffma2(lc, wB.x, o45);
            o67 = ffma2(lc, wB.y, o67);
        }
        float out[8];
        upk2(o01, out[0], out[1]); upk2(o23, out[2], out[3]);
        upk2(o45, out[4], out[5]); upk2(o67, out[6], out[7]);

        if (logits_out) {
            float4* lo = reinterpret_cast<float4*>(logits_out + (long)bz * Hn * Wn * Cn + gi);
            lo[0] = make_float4(out[0], out[1], out[2], out[3]);
            lo[1] = make_float4(out[4], out[5], out[6], out[7]);
        } else {
            float m = out[0];
#pragma unroll
            for (int c = 1; c < 8; c++) m = fmaxf(m, out[c]);
            float e[8], s = 0.f;
#pragma unroll
            for (int c = 0; c < 8; c++) { e[c] = __expf(out[c] - m); s += e[c]; }
            float inv = 1.f / s;
            float4* qp = reinterpret_cast<float4*>(qo + gi);
            qp[0] = make_float4(e[0] * inv, e[1] * inv, e[2] * inv, e[3] * inv);
            qp[1] = make_float4(e[4] * inv, e[5] * inv, e[6] * inv, e[7] * inv);
        }
    }
}

// ============================================================
// Launch: init + 5 fused iterations (NUM_ITERS fixed at 5)
// ============================================================
extern "C" void kernel_launch(void* const* d_in, const int* in_sizes, int n_in,
                              void* d_out, int out_size) {
    const float* x  = (const float*)d_in[0];
    const float* kw = (const float*)d_in[1];
    const float* ws = (const float*)d_in[2];
    const float* bs = (const float*)d_in[3];

    float *qA, *qB, *uu;
    cudaGetSymbolAddress((void**)&qA, g_qA);
    cudaGetSymbolAddress((void**)&qB, g_qB);
    cudaGetSymbolAddress((void**)&uu, g_u);

    k_init<<<(NPIX + 255) / 256, 256>>>(x, qA, uu);

    dim3 grid(Wn / TX, Hn / TY, Bn);   // (6, 48, 32)
    dim3 block(16, 8);

    float* src = qA;
    float* dst = qB;
    for (int it = 0; it < 5; it++) {
        float* lo = (it == 4) ? (float*)d_out : nullptr;
        k_iter<<<grid, block>>>(src, uu, kw, ws, bs, dst, lo);
        float* t = src; src = dst; dst = t;
    }
}

// round 4
// speedup vs baseline: 2.6839x; 2.6839x over previous
#include <cuda_runtime.h>
#include <cuda_fp16.h>
#include <cstdint>

#define Bn 32
#define Hn 384
#define Wn 384
#define NPIX (Bn*Hn*Wn)          // 4,718,592
#define NELEM (NPIX*8)           // 37,748,736

#define TILE_X 128
#define ROWS_PER 16
#define RPITCH 136               // smem row pitch in pixels

// Scratch (__device__ globals: allocation-free rule)
__device__ __half g_qA[NELEM];
__device__ __half g_qB[NELEM];
__device__ float  g_u[NELEM];

// ---------- helpers ----------
__device__ __forceinline__ uint32_t smem_u32(const void* p) {
    uint32_t a;
    asm("{ .reg .u64 t; cvta.to.shared.u64 t, %1; cvt.u32.u64 %0, t; }"
        : "=r"(a) : "l"(p));
    return a;
}
__device__ __forceinline__ void ldm4(uint32_t& a0, uint32_t& a1,
                                     uint32_t& a2, uint32_t& a3, uint32_t addr) {
    asm volatile("ldmatrix.sync.aligned.m8n8.x4.shared.b16 {%0,%1,%2,%3},[%4];"
                 : "=r"(a0), "=r"(a1), "=r"(a2), "=r"(a3) : "r"(addr));
}
__device__ __forceinline__ void hmma(float* d, uint32_t a0, uint32_t a1,
                                     uint32_t a2, uint32_t a3,
                                     uint32_t b0, uint32_t b1) {
    asm volatile("mma.sync.aligned.m16n8k16.row.col.f32.f16.f16.f32 "
                 "{%0,%1,%2,%3},{%4,%5,%6,%7},{%8,%9},{%0,%1,%2,%3};"
                 : "+f"(d[0]), "+f"(d[1]), "+f"(d[2]), "+f"(d[3])
                 : "r"(a0), "r"(a1), "r"(a2), "r"(a3), "r"(b0), "r"(b1));
}
// packed f32x2 FFMA
__device__ __forceinline__ unsigned long long pk2(float lo, float hi) {
    unsigned long long r;
    asm("mov.b64 %0,{%1,%2};" : "=l"(r) : "f"(lo), "f"(hi));
    return r;
}
__device__ __forceinline__ void upk2(unsigned long long v, float& lo, float& hi) {
    asm("mov.b64 {%0,%1},%2;" : "=f"(lo), "=f"(hi) : "l"(v));
}
__device__ __forceinline__ unsigned long long ffma2(unsigned long long a,
                                                    unsigned long long b,
                                                    unsigned long long c) {
    unsigned long long d;
    asm("fma.rn.f32x2 %0,%1,%2,%3;" : "=l"(d) : "l"(a), "l"(b), "l"(c));
    return d;
}
__device__ __forceinline__ uint32_t h2pack(float a, float b) {
    __half2 h = __floats2half2_rn(a, b);
    return *reinterpret_cast<uint32_t*>(&h);
}

// ============================================================
// init: q0 = softmax(x) (fp16), u = -log(max(q0,1e-6)) (fp32)
// ============================================================
__global__ void k_init(const float* __restrict__ x,
                       __half* __restrict__ q,
                       float* __restrict__ u) {
    int i = blockIdx.x * blockDim.x + threadIdx.x;
    if (i >= NPIX) return;
    const float4* xp = reinterpret_cast<const float4*>(x) + (long)i * 2;
    float4 a = xp[0], b4 = xp[1];
    float v[8] = {a.x, a.y, a.z, a.w, b4.x, b4.y, b4.z, b4.w};
    float m = v[0];
#pragma unroll
    for (int c = 1; c < 8; c++) m = fmaxf(m, v[c]);
    float e[8], s = 0.f;
#pragma unroll
    for (int c = 0; c < 8; c++) { e[c] = __expf(v[c] - m); s += e[c]; }
    float inv = 1.f / s;
    float qq[8];
#pragma unroll
    for (int c = 0; c < 8; c++) qq[c] = e[c] * inv;

    uint4 qv;
    qv.x = h2pack(qq[0], qq[1]);
    qv.y = h2pack(qq[2], qq[3]);
    qv.z = h2pack(qq[4], qq[5]);
    qv.w = h2pack(qq[6], qq[7]);
    reinterpret_cast<uint4*>(q)[i] = qv;

    float4* up = reinterpret_cast<float4*>(u) + (long)i * 2;
    up[0] = make_float4(-__logf(fmaxf(qq[0], 1e-6f)), -__logf(fmaxf(qq[1], 1e-6f)),
                        -__logf(fmaxf(qq[2], 1e-6f)), -__logf(fmaxf(qq[3], 1e-6f)));
    up[1] = make_float4(-__logf(fmaxf(qq[4], 1e-6f)), -__logf(fmaxf(qq[5], 1e-6f)),
                        -__logf(fmaxf(qq[6], 1e-6f)), -__logf(fmaxf(qq[7], 1e-6f)));
}

// ============================================================
// One mean-field iteration, implicit-GEMM conv via mma.sync.
// CTA: 128-px x-tile, 16 rows. 8-slot smem row ring.
// Per row: 28 tap-pairs, each m16n8k16 (K = 2 adjacent pixels x 8 ch).
// ============================================================
__global__ __launch_bounds__(128)
void k_iter(const __half* __restrict__ qin,
            const float* __restrict__ u,
            const float* __restrict__ kw,      // [7,7,8,8] fp32
            const float* __restrict__ wsc,     // [8,8]
            const float* __restrict__ bsc,     // [8]
            __half* __restrict__ qout,
            float* __restrict__ logits_out) {  // non-null on last iter
    __shared__ __align__(16) __half sq[8][RPITCH][8];   // ring: 17,408 B
    __shared__ __align__(16) uint2  sbfrag[7][4][32];   // B fragments: 7,168 B
    __shared__ __align__(16) float  sst[4][32][10];     // staging: 5,120 B
    __shared__ float swf[64];
    __shared__ float sbf[8];

    const int tid = threadIdx.x;
    const int w = tid >> 5;
    const int lane = tid & 31;

    // ---- B fragments: lane-indexed, diag-masked, dx=7 zeroed ----
    // b0 = {w[dy][2*dxp][2t][g], w[dy][2*dxp][2t+1][g]}
    // b1 = same with dx = 2*dxp+1 (0 if dx==7)
    for (int idx = tid; idx < 7 * 4 * 32; idx += 128) {
        int l = idx & 31, dxp = (idx >> 5) & 3, dy = idx >> 7;
        int t = l & 3, g = l >> 2;
        int dx0 = dxp * 2, dx1 = dx0 + 1;
        int c0 = 2 * t, c1 = 2 * t + 1;
        float w00 = (c0 == g) ? 0.f : kw[((dy * 7 + dx0) * 8 + c0) * 8 + g];
        float w01 = (c1 == g) ? 0.f : kw[((dy * 7 + dx0) * 8 + c1) * 8 + g];
        float w10 = 0.f, w11 = 0.f;
        if (dx1 < 7) {
            w10 = (c0 == g) ? 0.f : kw[((dy * 7 + dx1) * 8 + c0) * 8 + g];
            w11 = (c1 == g) ? 0.f : kw[((dy * 7 + dx1) * 8 + c1) * 8 + g];
        }
        sbfrag[dy][dxp][l] = make_uint2(h2pack(w00, w01), h2pack(w10, w11));
    }
    if (tid < 64) swf[tid] = wsc[tid];
    if (tid < 8)  sbf[tid] = bsc[tid];
    if (tid < 16) {  // zero slack pixels s=134,135 of each ring slot
        uint4 z = make_uint4(0, 0, 0, 0);
        *reinterpret_cast<uint4*>(&sq[tid >> 1][134 + (tid & 1)][0]) = z;
    }

    const int x0 = blockIdx.x * TILE_X;
    const int y0 = blockIdx.y * ROWS_PER;
    const int bz = blockIdx.z;
    const uint4* qb = reinterpret_cast<const uint4*>(qin) + (long)bz * Hn * Wn;

    auto load_row = [&](int gy) {
        uint4* dst = reinterpret_cast<uint4*>(&sq[gy & 7][0][0]);
        if ((unsigned)gy < (unsigned)Hn) {
            const uint4* src = qb + (long)gy * Wn;
            for (int i = tid; i < 134; i += 128) {
                int gx = x0 - 3 + i;
                uint4 v = make_uint4(0, 0, 0, 0);
                if ((unsigned)gx < (unsigned)Wn) v = src[gx];
                dst[i] = v;
            }
        } else {
            uint4 z = make_uint4(0, 0, 0, 0);
            for (int i = tid; i < 134; i += 128) dst[i] = z;
        }
    };

    for (int gy = y0 - 3; gy < y0 + 3; ++gy) load_row(gy);
    __syncthreads();

    const uint32_t ring0 = smem_u32(sq);
    // per-lane ldmatrix offset: row (l&15), col-block (l>>4) -> +1 pixel
    const uint32_t lofs = (uint32_t)(((lane & 15) + (lane >> 4)) * 16);
    const uint32_t wbase = (uint32_t)(w * 32 * 16);  // warp pixel base (bytes)

    for (int r = 0; r < ROWS_PER; ++r) {
        const int y = y0 + r;
        load_row(y + 3);
        __syncthreads();

        float acc0[4] = {0.f, 0.f, 0.f, 0.f};
        float acc1[4] = {0.f, 0.f, 0.f, 0.f};
#pragma unroll
        for (int dy = 0; dy < 7; ++dy) {
            const uint32_t rbase =
                ring0 + (uint32_t)(((y + dy - 3) & 7) * (RPITCH * 16)) + wbase + lofs;
#pragma unroll
            for (int dxp = 0; dxp < 4; ++dxp) {
                uint2 bf = sbfrag[dy][dxp][lane];
                uint32_t abase = rbase + (uint32_t)(dxp * 32);
                uint32_t a0, a1, a2, a3;
                ldm4(a0, a1, a2, a3, abase);
                hmma(acc0, a0, a1, a2, a3, bf.x, bf.y);
                ldm4(a0, a1, a2, a3, abase + 256);
                hmma(acc1, a0, a1, a2, a3, bf.x, bf.y);
            }
        }

        // ---- transpose D through staging: lane -> one pixel's 8 channels ----
        const int g = lane >> 2, t = lane & 3;
        __syncwarp();
        *reinterpret_cast<float2*>(&sst[w][g][2 * t])      = make_float2(acc0[0], acc0[1]);
        *reinterpret_cast<float2*>(&sst[w][g + 8][2 * t])  = make_float2(acc0[2], acc0[3]);
        *reinterpret_cast<float2*>(&sst[w][g + 16][2 * t]) = make_float2(acc1[0], acc1[1]);
        *reinterpret_cast<float2*>(&sst[w][g + 24][2 * t]) = make_float2(acc1[2], acc1[3]);
        __syncwarp();
        float pen[8];
#pragma unroll
        for (int c = 0; c < 4; ++c) {
            float2 v = *reinterpret_cast<float2*>(&sst[w][lane][2 * c]);
            pen[2 * c] = v.x; pen[2 * c + 1] = v.y;
        }

        const long gi = ((long)(bz * Hn + y) * Wn + x0 + w * 32 + lane) * 8;
        float4 uA = *reinterpret_cast<const float4*>(u + gi);
        float4 uB = *reinterpret_cast<const float4*>(u + gi + 4);
        float lg[8];
        lg[0] = -(uA.x + pen[0]); lg[1] = -(uA.y + pen[1]);
        lg[2] = -(uA.z + pen[2]); lg[3] = -(uA.w + pen[3]);
        lg[4] = -(uB.x + pen[4]); lg[5] = -(uB.y + pen[5]);
        lg[6] = -(uB.z + pen[6]); lg[7] = -(uB.w + pen[7]);

        // 1x1: out[d] = sum_c lg[c]*W[c][d] + b[d]  (packed FFMA2)
        unsigned long long o01 = pk2(sbf[0], sbf[1]);
        unsigned long long o23 = pk2(sbf[2], sbf[3]);
        unsigned long long o45 = pk2(sbf[4], sbf[5]);
        unsigned long long o67 = pk2(sbf[6], sbf[7]);
#pragma unroll
        for (int c = 0; c < 8; c++) {
            const ulonglong2* wp = reinterpret_cast<const ulonglong2*>(&swf[c * 8]);
            ulonglong2 wA = wp[0], wB = wp[1];
            unsigned long long lc = pk2(lg[c], lg[c]);
            o01 = ffma2(lc, wA.x, o01);
            o23 = ffma2(lc, wA.y, o23);
            o45 = ffma2(lc, wB.x, o45);
            o67 = ffma2(lc, wB.y, o67);
        }
        float out[8];
        upk2(o01, out[0], out[1]); upk2(o23, out[2], out[3]);
        upk2(o45, out[4], out[5]); upk2(o67, out[6], out[7]);

        if (logits_out) {
            float4* lo = reinterpret_cast<float4*>(logits_out + gi);
            lo[0] = make_float4(out[0], out[1], out[2], out[3]);
            lo[1] = make_float4(out[4], out[5], out[6], out[7]);
        } else {
            float m = out[0];
#pragma unroll
            for (int c = 1; c < 8; c++) m = fmaxf(m, out[c]);
            float e[8], s = 0.f;
#pragma unroll
            for (int c = 0; c < 8; c++) { e[c] = __expf(out[c] - m); s += e[c]; }
            float inv = 1.f / s;
            uint4 qv;
            qv.x = h2pack(e[0] * inv, e[1] * inv);
            qv.y = h2pack(e[2] * inv, e[3] * inv);
            qv.z = h2pack(e[4] * inv, e[5] * inv);
            qv.w = h2pack(e[6] * inv, e[7] * inv);
            reinterpret_cast<uint4*>(qout)[gi >> 3] = qv;
        }
    }
}

// ============================================================
extern "C" void kernel_launch(void* const* d_in, const int* in_sizes, int n_in,
                              void* d_out, int out_size) {
    const float* x  = (const float*)d_in[0];
    const float* kw = (const float*)d_in[1];
    const float* ws = (const float*)d_in[2];
    const float* bs = (const float*)d_in[3];

    __half *qA, *qB;
    float* uu;
    cudaGetSymbolAddress((void**)&qA, g_qA);
    cudaGetSymbolAddress((void**)&qB, g_qB);
    cudaGetSymbolAddress((void**)&uu, g_u);

    k_init<<<(NPIX + 255) / 256, 256>>>(x, qA, uu);

    dim3 grid(Wn / TILE_X, Hn / ROWS_PER, Bn);   // (3, 24, 32) = 2304 CTAs
    __half* src = qA;
    __half* dst = qB;
    for (int it = 0; it < 5; it++) {
        float* lo = (it == 4) ? (float*)d_out : nullptr;
        k_iter<<<grid, 128>>>(src, uu, kw, ws, bs, dst, lo);
        __half* t = src; src = dst; dst = t;
    }
}

// round 7
// speedup vs baseline: 4.5131x; 1.6816x over previous
#include <cuda_runtime.h>
#include <cuda_fp16.h>
#include <cstdint>

#define Bn 32
#define Hn 384
#define Wn 384
#define NPIX (Bn*Hn*Wn)          // 4,718,592
#define NELEM (NPIX*8)           // 37,748,736

#define TILE_X 128
#define ROWS_PER 16              // per CTA
#define RPASS 4                  // output rows per pass
#define RPITCH 136               // smem row pitch in pixels
#define RING 16                  // ring slots (pow2)

// Scratch (__device__ globals: allocation-free rule)
__device__ __half g_qA[NELEM];
__device__ __half g_qB[NELEM];
__device__ float  g_u[NELEM];

// ---------- helpers ----------
__device__ __forceinline__ uint32_t smem_u32(const void* p) {
    uint32_t a;
    asm("{ .reg .u64 t; cvta.to.shared.u64 t, %1; cvt.u32.u64 %0, t; }"
        : "=r"(a) : "l"(p));
    return a;
}
__device__ __forceinline__ void ldm4(uint32_t& a0, uint32_t& a1,
                                     uint32_t& a2, uint32_t& a3, uint32_t addr) {
    asm volatile("ldmatrix.sync.aligned.m8n8.x4.shared.b16 {%0,%1,%2,%3},[%4];"
                 : "=r"(a0), "=r"(a1), "=r"(a2), "=r"(a3) : "r"(addr));
}
__device__ __forceinline__ void hmma(float* d, uint32_t a0, uint32_t a1,
                                     uint32_t a2, uint32_t a3,
                                     uint32_t b0, uint32_t b1) {
    asm volatile("mma.sync.aligned.m16n8k16.row.col.f32.f16.f16.f32 "
                 "{%0,%1,%2,%3},{%4,%5,%6,%7},{%8,%9},{%0,%1,%2,%3};"
                 : "+f"(d[0]), "+f"(d[1]), "+f"(d[2]), "+f"(d[3])
                 : "r"(a0), "r"(a1), "r"(a2), "r"(a3), "r"(b0), "r"(b1));
}
__device__ __forceinline__ void cpa16(uint32_t dst, const void* src, int sz) {
    asm volatile("cp.async.cg.shared.global [%0], [%1], 16, %2;"
                 :: "r"(dst), "l"(src), "r"(sz) : "memory");
}
__device__ __forceinline__ void cpa_commit() {
    asm volatile("cp.async.commit_group;" ::: "memory");
}
__device__ __forceinline__ void cpa_wait0() {
    asm volatile("cp.async.wait_group 0;" ::: "memory");
}
// packed f32x2 FFMA
__device__ __forceinline__ unsigned long long pk2(float lo, float hi) {
    unsigned long long r;
    asm("mov.b64 %0,{%1,%2};" : "=l"(r) : "f"(lo), "f"(hi));
    return r;
}
__device__ __forceinline__ void upk2(unsigned long long v, float& lo, float& hi) {
    asm("mov.b64 {%0,%1},%2;" : "=f"(lo), "=f"(hi) : "l"(v));
}
__device__ __forceinline__ unsigned long long ffma2(unsigned long long a,
                                                    unsigned long long b,
                                                    unsigned long long c) {
    unsigned long long d;
    asm("fma.rn.f32x2 %0,%1,%2,%3;" : "=l"(d) : "l"(a), "l"(b), "l"(c));
    return d;
}
__device__ __forceinline__ uint32_t h2pack(float a, float b) {
    __half2 h = __floats2half2_rn(a, b);
    return *reinterpret_cast<uint32_t*>(&h);
}

// ============================================================
// init: q0 = softmax(x) (fp16), u = -log(max(q0,1e-6)) (fp32)
// ============================================================
__global__ void k_init(const float* __restrict__ x,
                       __half* __restrict__ q,
                       float* __restrict__ u) {
    int i = blockIdx.x * blockDim.x + threadIdx.x;
    if (i >= NPIX) return;
    const float4* xp = reinterpret_cast<const float4*>(x) + (long)i * 2;
    float4 a = xp[0], b4 = xp[1];
    float v[8] = {a.x, a.y, a.z, a.w, b4.x, b4.y, b4.z, b4.w};
    float m = v[0];
#pragma unroll
    for (int c = 1; c < 8; c++) m = fmaxf(m, v[c]);
    float e[8], s = 0.f;
#pragma unroll
    for (int c = 0; c < 8; c++) { e[c] = __expf(v[c] - m); s += e[c]; }
    float inv = 1.f / s;
    float qq[8];
#pragma unroll
    for (int c = 0; c < 8; c++) qq[c] = e[c] * inv;

    uint4 qv;
    qv.x = h2pack(qq[0], qq[1]);
    qv.y = h2pack(qq[2], qq[3]);
    qv.z = h2pack(qq[4], qq[5]);
    qv.w = h2pack(qq[6], qq[7]);
    reinterpret_cast<uint4*>(q)[i] = qv;

    float4* up = reinterpret_cast<float4*>(u) + (long)i * 2;
    up[0] = make_float4(-__logf(fmaxf(qq[0], 1e-6f)), -__logf(fmaxf(qq[1], 1e-6f)),
                        -__logf(fmaxf(qq[2], 1e-6f)), -__logf(fmaxf(qq[3], 1e-6f)));
    up[1] = make_float4(-__logf(fmaxf(qq[4], 1e-6f)), -__logf(fmaxf(qq[5], 1e-6f)),
                        -__logf(fmaxf(qq[6], 1e-6f)), -__logf(fmaxf(qq[7], 1e-6f)));
}

// ============================================================
// One mean-field iteration. Implicit-GEMM conv via mma.sync,
// 4 output rows per pass: each ldmatrix feeds up to 4 HMMAs.
// cp.async prefetch of next pass's rows into a 16-slot ring.
// ============================================================
__global__ __launch_bounds__(128)
void k_iter(const __half* __restrict__ qin,
            const float* __restrict__ u,
            const float* __restrict__ kw,      // [7,7,8,8] fp32
            const float* __restrict__ wsc,     // [8,8]
            const float* __restrict__ bsc,     // [8]
            __half* __restrict__ qout,
            float* __restrict__ logits_out) {  // non-null on last iter
    __shared__ __align__(16) __half sq[RING][RPITCH][8];  // 34,816 B
    __shared__ __align__(16) uint2  sbfrag[7][4][32];     // 7,168 B
    __shared__ __align__(16) float  sst[4][32][10];       // 5,120 B
    __shared__ float swf[64];
    __shared__ float sbf[8];

    const int tid = threadIdx.x;
    const int w = tid >> 5;
    const int lane = tid & 31;

    // ---- B fragments: lane-indexed, diag-masked, dx=7 zeroed ----
    for (int idx = tid; idx < 7 * 4 * 32; idx += 128) {
        int l = idx & 31, dxp = (idx >> 5) & 3, dy = idx >> 7;
        int t = l & 3, g = l >> 2;
        int dx0 = dxp * 2, dx1 = dx0 + 1;
        int c0 = 2 * t, c1 = 2 * t + 1;
        float w00 = (c0 == g) ? 0.f : kw[((dy * 7 + dx0) * 8 + c0) * 8 + g];
        float w01 = (c1 == g) ? 0.f : kw[((dy * 7 + dx0) * 8 + c1) * 8 + g];
        float w10 = 0.f, w11 = 0.f;
        if (dx1 < 7) {
            w10 = (c0 == g) ? 0.f : kw[((dy * 7 + dx1) * 8 + c0) * 8 + g];
            w11 = (c1 == g) ? 0.f : kw[((dy * 7 + dx1) * 8 + c1) * 8 + g];
        }
        sbfrag[dy][dxp][l] = make_uint2(h2pack(w00, w01), h2pack(w10, w11));
    }
    if (tid < 64) swf[tid] = wsc[tid];
    if (tid < 8)  sbf[tid] = bsc[tid];
    if (tid < 2 * RING) {  // zero slack pixels 134,135 of every ring slot
        uint4 z = make_uint4(0, 0, 0, 0);
        *reinterpret_cast<uint4*>(&sq[tid >> 1][134 + (tid & 1)][0]) = z;
    }

    const int x0 = blockIdx.x * TILE_X;
    const int y0 = blockIdx.y * ROWS_PER;
    const int bz = blockIdx.z;
    const uint4* qb = reinterpret_cast<const uint4*>(qin) + (long)bz * Hn * Wn;

    auto async_row = [&](int gy) {
        uint32_t dst0 = smem_u32(&sq[gy & (RING - 1)][0][0]);
        const bool rowok = (unsigned)gy < (unsigned)Hn;
        const int gyc = rowok ? gy : 0;
        const uint4* rowp = qb + (long)gyc * Wn;
        for (int i = tid; i < 134; i += 128) {
            int gx = x0 - 3 + i;
            bool ok = rowok && (unsigned)gx < (unsigned)Wn;
            int gxc = ((unsigned)gx < (unsigned)Wn) ? gx : 0;
            // sz=0 lanes zero-fill dst; src stays a valid clamped address
            cpa16(dst0 + (uint32_t)i * 16u, rowp + gxc, ok ? 16 : 0);
        }
    };

    // preload the 10 rows for pass 0
    for (int gy = y0 - 3; gy <= y0 + 6; ++gy) async_row(gy);
    cpa_commit();
    cpa_wait0();
    __syncthreads();

    const uint32_t ring0 = smem_u32(sq);
    const uint32_t lofs = (uint32_t)(((lane & 15) + (lane >> 4)) * 16);
    const uint32_t wbase = (uint32_t)(w * 32 * 16);

    for (int p = 0; p < ROWS_PER / RPASS; ++p) {
        const int y = y0 + p * RPASS;
        if (p < ROWS_PER / RPASS - 1) {  // prefetch next pass's 4 rows
            for (int gy = y + 7; gy <= y + 10; ++gy) async_row(gy);
            cpa_commit();
        }

        float acc[RPASS][8];
#pragma unroll
        for (int r = 0; r < RPASS; ++r)
#pragma unroll
            for (int j = 0; j < 8; ++j) acc[r][j] = 0.f;

#pragma unroll
        for (int si = 0; si < 10; ++si) {
            const int sy = si - 3;                        // input row rel. to y
            const int slot = (y + sy) & (RING - 1);
            const uint32_t rbase = ring0 + (uint32_t)(slot * (RPITCH * 16)) + wbase + lofs;
            const int rlo = (sy - 3 < 0) ? 0 : sy - 3;
            const int rhi = (sy + 3 > RPASS - 1) ? RPASS - 1 : sy + 3;
#pragma unroll
            for (int dxp = 0; dxp < 4; ++dxp) {
                uint32_t a0, a1, a2, a3, c0, c1, c2, c3;
                ldm4(a0, a1, a2, a3, rbase + (uint32_t)(dxp * 32));
                ldm4(c0, c1, c2, c3, rbase + (uint32_t)(dxp * 32) + 256);
#pragma unroll
                for (int r = rlo; r <= rhi; ++r) {
                    const int dy = sy - r + 3;            // 0..6, compile-time
                    uint2 bf = sbfrag[dy][dxp][lane];
                    hmma(acc[r], a0, a1, a2, a3, bf.x, bf.y);
                    hmma(acc[r] + 4, c0, c1, c2, c3, bf.x, bf.y);
                }
            }
        }

        // ---- epilogue: 4 rows ----
        const int g = lane >> 2, t = lane & 3;
#pragma unroll
        for (int r = 0; r < RPASS; ++r) {
            __syncwarp();
            *reinterpret_cast<float2*>(&sst[w][g][2 * t])      = make_float2(acc[r][0], acc[r][1]);
            *reinterpret_cast<float2*>(&sst[w][g + 8][2 * t])  = make_float2(acc[r][2], acc[r][3]);
            *reinterpret_cast<float2*>(&sst[w][g + 16][2 * t]) = make_float2(acc[r][4], acc[r][5]);
            *reinterpret_cast<float2*>(&sst[w][g + 24][2 * t]) = make_float2(acc[r][6], acc[r][7]);
            __syncwarp();
            float pen[8];
#pragma unroll
            for (int c = 0; c < 4; ++c) {
                float2 v = *reinterpret_cast<float2*>(&sst[w][lane][2 * c]);
                pen[2 * c] = v.x; pen[2 * c + 1] = v.y;
            }

            const long gi = ((long)(bz * Hn + y + r) * Wn + x0 + w * 32 + lane) * 8;
            float4 uA = *reinterpret_cast<const float4*>(u + gi);
            float4 uB = *reinterpret_cast<const float4*>(u + gi + 4);
            float lg[8];
            lg[0] = -(uA.x + pen[0]); lg[1] = -(uA.y + pen[1]);
            lg[2] = -(uA.z + pen[2]); lg[3] = -(uA.w + pen[3]);
            lg[4] = -(uB.x + pen[4]); lg[5] = -(uB.y + pen[5]);
            lg[6] = -(uB.z + pen[6]); lg[7] = -(uB.w + pen[7]);

            unsigned long long o01 = pk2(sbf[0], sbf[1]);
            unsigned long long o23 = pk2(sbf[2], sbf[3]);
            unsigned long long o45 = pk2(sbf[4], sbf[5]);
            unsigned long long o67 = pk2(sbf[6], sbf[7]);
#pragma unroll
            for (int c = 0; c < 8; c++) {
                const ulonglong2* wp = reinterpret_cast<const ulonglong2*>(&swf[c * 8]);
                ulonglong2 wA = wp[0], wB = wp[1];
                unsigned long long lc = pk2(lg[c], lg[c]);
                o01 = ffma2(lc, wA.x, o01);
                o23 = ffma2(lc, wA.y, o23);
                o45 = ffma2(lc, wB.x, o45);
                o67 = ffma2(lc, wB.y, o67);
            }
            float out[8];
            upk2(o01, out[0], out[1]); upk2(o23, out[2], out[3]);
            upk2(o45, out[4], out[5]); upk2(o67, out[6], out[7]);

            if (logits_out) {
                float4* lo = reinterpret_cast<float4*>(logits_out + gi);
                lo[0] = make_float4(out[0], out[1], out[2], out[3]);
                lo[1] = make_float4(out[4], out[5], out[6], out[7]);
            } else {
                float m = out[0];
#pragma unroll
                for (int c = 1; c < 8; c++) m = fmaxf(m, out[c]);
                float e[8], s = 0.f;
#pragma unroll
                for (int c = 0; c < 8; c++) { e[c] = __expf(out[c] - m); s += e[c]; }
                float inv = 1.f / s;
                uint4 qv;
                qv.x = h2pack(e[0] * inv, e[1] * inv);
                qv.y = h2pack(e[2] * inv, e[3] * inv);
                qv.z = h2pack(e[4] * inv, e[5] * inv);
                qv.w = h2pack(e[6] * inv, e[7] * inv);
                reinterpret_cast<uint4*>(qout)[gi >> 3] = qv;
            }
        }

        if (p < ROWS_PER / RPASS - 1) cpa_wait0();
        __syncthreads();
    }
}

// ============================================================
extern "C" void kernel_launch(void* const* d_in, const int* in_sizes, int n_in,
                              void* d_out, int out_size) {
    const float* x  = (const float*)d_in[0];
    const float* kw = (const float*)d_in[1];
    const float* ws = (const float*)d_in[2];
    const float* bs = (const float*)d_in[3];

    __half *qA, *qB;
    float* uu;
    cudaGetSymbolAddress((void**)&qA, g_qA);
    cudaGetSymbolAddress((void**)&qB, g_qB);
    cudaGetSymbolAddress((void**)&uu, g_u);

    k_init<<<(NPIX + 255) / 256, 256>>>(x, qA, uu);

    dim3 grid(Wn / TILE_X, Hn / ROWS_PER, Bn);   // (3, 24, 32) = 2304 CTAs
    __half* src = qA;
    __half* dst = qB;
    for (int it = 0; it < 5; it++) {
        float* lo = (it == 4) ? (float*)d_out : nullptr;
        k_iter<<<grid, 128>>>(src, uu, kw, ws, bs, dst, lo);
        __half* t = src; src = dst; dst = t;
    }
}

// round 8
// speedup vs baseline: 4.6259x; 1.0250x over previous
#include <cuda_runtime.h>
#include <cuda_fp16.h>
#include <cstdint>

#define Bn 32
#define Hn 384
#define Wn 384
#define NPIX (Bn*Hn*Wn)          // 4,718,592
#define NELEM (NPIX*8)           // 37,748,736

#define TILE_X 128
#define ROWS_PER 16              // per CTA
#define RPASS 4                  // output rows per pass
#define RPITCH 136               // smem row pitch in pixels
#define RING 16                  // ring slots (pow2)

// Scratch (__device__ globals: allocation-free rule)
__device__ __half g_qA[NELEM];
__device__ __half g_qB[NELEM];
__device__ float  g_u[NELEM];

// ---------- helpers ----------
__device__ __forceinline__ uint32_t smem_u32(const void* p) {
    uint32_t a;
    asm("{ .reg .u64 t; cvta.to.shared.u64 t, %1; cvt.u32.u64 %0, t; }"
        : "=r"(a) : "l"(p));
    return a;
}
__device__ __forceinline__ void ldm4(uint32_t& a0, uint32_t& a1,
                                     uint32_t& a2, uint32_t& a3, uint32_t addr) {
    asm volatile("ldmatrix.sync.aligned.m8n8.x4.shared.b16 {%0,%1,%2,%3},[%4];"
                 : "=r"(a0), "=r"(a1), "=r"(a2), "=r"(a3) : "r"(addr));
}
__device__ __forceinline__ void hmma(float* d, uint32_t a0, uint32_t a1,
                                     uint32_t a2, uint32_t a3,
                                     uint32_t b0, uint32_t b1) {
    asm volatile("mma.sync.aligned.m16n8k16.row.col.f32.f16.f16.f32 "
                 "{%0,%1,%2,%3},{%4,%5,%6,%7},{%8,%9},{%0,%1,%2,%3};"
                 : "+f"(d[0]), "+f"(d[1]), "+f"(d[2]), "+f"(d[3])
                 : "r"(a0), "r"(a1), "r"(a2), "r"(a3), "r"(b0), "r"(b1));
}
__device__ __forceinline__ void cpa16(uint32_t dst, const void* src, int sz) {
    asm volatile("cp.async.cg.shared.global [%0], [%1], 16, %2;"
                 :: "r"(dst), "l"(src), "r"(sz) : "memory");
}
__device__ __forceinline__ void cpa_commit() {
    asm volatile("cp.async.commit_group;" ::: "memory");
}
__device__ __forceinline__ void cpa_wait0() {
    asm volatile("cp.async.wait_group 0;" ::: "memory");
}
// packed f32x2 FFMA
__device__ __forceinline__ unsigned long long pk2(float lo, float hi) {
    unsigned long long r;
    asm("mov.b64 %0,{%1,%2};" : "=l"(r) : "f"(lo), "f"(hi));
    return r;
}
__device__ __forceinline__ void upk2(unsigned long long v, float& lo, float& hi) {
    asm("mov.b64 {%0,%1},%2;" : "=f"(lo), "=f"(hi) : "l"(v));
}
__device__ __forceinline__ unsigned long long ffma2(unsigned long long a,
                                                    unsigned long long b,
                                                    unsigned long long c) {
    unsigned long long d;
    asm("fma.rn.f32x2 %0,%1,%2,%3;" : "=l"(d) : "l"(a), "l"(b), "l"(c));
    return d;
}
__device__ __forceinline__ uint32_t h2pack(float a, float b) {
    __half2 h = __floats2half2_rn(a, b);
    return *reinterpret_cast<uint32_t*>(&h);
}

// ============================================================
// init: q0 = softmax(x) (fp16), u = -log(max(q0,1e-6)) (fp32)
// ============================================================
__global__ void k_init(const float* __restrict__ x,
                       __half* __restrict__ q,
                       float* __restrict__ u) {
    int i = blockIdx.x * blockDim.x + threadIdx.x;
    if (i >= NPIX) return;
    const float4* xp = reinterpret_cast<const float4*>(x) + (long)i * 2;
    float4 a = xp[0], b4 = xp[1];
    float v[8] = {a.x, a.y, a.z, a.w, b4.x, b4.y, b4.z, b4.w};
    float m = v[0];
#pragma unroll
    for (int c = 1; c < 8; c++) m = fmaxf(m, v[c]);
    float e[8], s = 0.f;
#pragma unroll
    for (int c = 0; c < 8; c++) { e[c] = __expf(v[c] - m); s += e[c]; }
    float inv = 1.f / s;
    float qq[8];
#pragma unroll
    for (int c = 0; c < 8; c++) qq[c] = e[c] * inv;

    uint4 qv;
    qv.x = h2pack(qq[0], qq[1]);
    qv.y = h2pack(qq[2], qq[3]);
    qv.z = h2pack(qq[4], qq[5]);
    qv.w = h2pack(qq[6], qq[7]);
    reinterpret_cast<uint4*>(q)[i] = qv;

    float4* up = reinterpret_cast<float4*>(u) + (long)i * 2;
    up[0] = make_float4(-__logf(fmaxf(qq[0], 1e-6f)), -__logf(fmaxf(qq[1], 1e-6f)),
                        -__logf(fmaxf(qq[2], 1e-6f)), -__logf(fmaxf(qq[3], 1e-6f)));
    up[1] = make_float4(-__logf(fmaxf(qq[4], 1e-6f)), -__logf(fmaxf(qq[5], 1e-6f)),
                        -__logf(fmaxf(qq[6], 1e-6f)), -__logf(fmaxf(qq[7], 1e-6f)));
}

// ============================================================
// One mean-field iteration. Implicit-GEMM conv via mma.sync.
// 4 output rows per pass; dxp-outer loop keeps that dxp's 7 B
// fragments in registers (28 B-frag LDS per pass, was 112).
// cp.async prefetch of next pass's rows into a 16-slot ring.
// ============================================================
__global__ __launch_bounds__(128)
void k_iter(const __half* __restrict__ qin,
            const float* __restrict__ u,
            const float* __restrict__ kw,      // [7,7,8,8] fp32
            const float* __restrict__ wsc,     // [8,8]
            const float* __restrict__ bsc,     // [8]
            __half* __restrict__ qout,
            float* __restrict__ logits_out) {  // non-null on last iter
    __shared__ __align__(16) __half sq[RING][RPITCH][8];  // 34,816 B
    __shared__ __align__(16) uint2  sbfrag[7][4][32];     // 7,168 B
    __shared__ __align__(16) float  sst[4][32][10];       // 5,120 B
    __shared__ float swf[64];
    __shared__ float sbf[8];

    const int tid = threadIdx.x;
    const int w = tid >> 5;
    const int lane = tid & 31;

    // ---- B fragments: lane-indexed, diag-masked, dx=7 zeroed ----
    for (int idx = tid; idx < 7 * 4 * 32; idx += 128) {
        int l = idx & 31, dxp = (idx >> 5) & 3, dy = idx >> 7;
        int t = l & 3, g = l >> 2;
        int dx0 = dxp * 2, dx1 = dx0 + 1;
        int c0 = 2 * t, c1 = 2 * t + 1;
        float w00 = (c0 == g) ? 0.f : kw[((dy * 7 + dx0) * 8 + c0) * 8 + g];
        float w01 = (c1 == g) ? 0.f : kw[((dy * 7 + dx0) * 8 + c1) * 8 + g];
        float w10 = 0.f, w11 = 0.f;
        if (dx1 < 7) {
            w10 = (c0 == g) ? 0.f : kw[((dy * 7 + dx1) * 8 + c0) * 8 + g];
            w11 = (c1 == g) ? 0.f : kw[((dy * 7 + dx1) * 8 + c1) * 8 + g];
        }
        sbfrag[dy][dxp][l] = make_uint2(h2pack(w00, w01), h2pack(w10, w11));
    }
    if (tid < 64) swf[tid] = wsc[tid];
    if (tid < 8)  sbf[tid] = bsc[tid];
    if (tid < 2 * RING) {  // zero slack pixels 134,135 of every ring slot
        uint4 z = make_uint4(0, 0, 0, 0);
        *reinterpret_cast<uint4*>(&sq[tid >> 1][134 + (tid & 1)][0]) = z;
    }

    const int x0 = blockIdx.x * TILE_X;
    const int y0 = blockIdx.y * ROWS_PER;
    const int bz = blockIdx.z;
    const uint4* qb = reinterpret_cast<const uint4*>(qin) + (long)bz * Hn * Wn;

    auto async_row = [&](int gy) {
        uint32_t dst0 = smem_u32(&sq[gy & (RING - 1)][0][0]);
        const bool rowok = (unsigned)gy < (unsigned)Hn;
        const int gyc = rowok ? gy : 0;
        const uint4* rowp = qb + (long)gyc * Wn;
        for (int i = tid; i < 134; i += 128) {
            int gx = x0 - 3 + i;
            bool ok = rowok && (unsigned)gx < (unsigned)Wn;
            int gxc = ((unsigned)gx < (unsigned)Wn) ? gx : 0;
            cpa16(dst0 + (uint32_t)i * 16u, rowp + gxc, ok ? 16 : 0);
        }
    };

    // preload the 10 rows for pass 0
    for (int gy = y0 - 3; gy <= y0 + 6; ++gy) async_row(gy);
    cpa_commit();
    cpa_wait0();
    __syncthreads();

    const uint32_t ring0 = smem_u32(sq);
    const uint32_t lofs = (uint32_t)(((lane & 15) + (lane >> 4)) * 16);
    const uint32_t wbase = (uint32_t)(w * 32 * 16);

    for (int p = 0; p < ROWS_PER / RPASS; ++p) {
        const int y = y0 + p * RPASS;
        if (p < ROWS_PER / RPASS - 1) {  // prefetch next pass's 4 rows
            for (int gy = y + 7; gy <= y + 10; ++gy) async_row(gy);
            cpa_commit();
        }

        float acc[RPASS][8];
#pragma unroll
        for (int r = 0; r < RPASS; ++r)
#pragma unroll
            for (int j = 0; j < 8; ++j) acc[r][j] = 0.f;

#pragma unroll
        for (int dxp = 0; dxp < 4; ++dxp) {
            uint2 bf[7];                 // this dxp's 7 dy fragments, in regs
#pragma unroll
            for (int dy = 0; dy < 7; ++dy) bf[dy] = sbfrag[dy][dxp][lane];

#pragma unroll
            for (int si = 0; si < 10; ++si) {
                const int sy = si - 3;                    // input row rel. to y
                const int slot = (y + sy) & (RING - 1);
                const uint32_t abase = ring0 + (uint32_t)(slot * (RPITCH * 16))
                                     + wbase + lofs + (uint32_t)(dxp * 32);
                uint32_t a0, a1, a2, a3, c0, c1, c2, c3;
                ldm4(a0, a1, a2, a3, abase);
                ldm4(c0, c1, c2, c3, abase + 256);
                const int rlo = (sy - 3 < 0) ? 0 : sy - 3;
                const int rhi = (sy + 3 > RPASS - 1) ? RPASS - 1 : sy + 3;
#pragma unroll
                for (int r = rlo; r <= rhi; ++r) {
                    const int dy = sy - r + 3;            // 0..6, compile-time
                    hmma(acc[r], a0, a1, a2, a3, bf[dy].x, bf[dy].y);
                    hmma(acc[r] + 4, c0, c1, c2, c3, bf[dy].x, bf[dy].y);
                }
            }
        }

        // ---- epilogue: 4 rows ----
        const int g = lane >> 2, t = lane & 3;
#pragma unroll
        for (int r = 0; r < RPASS; ++r) {
            __syncwarp();
            *reinterpret_cast<float2*>(&sst[w][g][2 * t])      = make_float2(acc[r][0], acc[r][1]);
            *reinterpret_cast<float2*>(&sst[w][g + 8][2 * t])  = make_float2(acc[r][2], acc[r][3]);
            *reinterpret_cast<float2*>(&sst[w][g + 16][2 * t]) = make_float2(acc[r][4], acc[r][5]);
            *reinterpret_cast<float2*>(&sst[w][g + 24][2 * t]) = make_float2(acc[r][6], acc[r][7]);
            __syncwarp();
            float pen[8];
#pragma unroll
            for (int c = 0; c < 4; ++c) {
                float2 v = *reinterpret_cast<float2*>(&sst[w][lane][2 * c]);
                pen[2 * c] = v.x; pen[2 * c + 1] = v.y;
            }

            const long gi = ((long)(bz * Hn + y + r) * Wn + x0 + w * 32 + lane) * 8;
            float4 uA = *reinterpret_cast<const float4*>(u + gi);
            float4 uB = *reinterpret_cast<const float4*>(u + gi + 4);
            float lg[8];
            lg[0] = -(uA.x + pen[0]); lg[1] = -(uA.y + pen[1]);
            lg[2] = -(uA.z + pen[2]); lg[3] = -(uA.w + pen[3]);
            lg[4] = -(uB.x + pen[4]); lg[5] = -(uB.y + pen[5]);
            lg[6] = -(uB.z + pen[6]); lg[7] = -(uB.w + pen[7]);

            unsigned long long o01 = pk2(sbf[0], sbf[1]);
            unsigned long long o23 = pk2(sbf[2], sbf[3]);
            unsigned long long o45 = pk2(sbf[4], sbf[5]);
            unsigned long long o67 = pk2(sbf[6], sbf[7]);
#pragma unroll
            for (int c = 0; c < 8; c++) {
                const ulonglong2* wp = reinterpret_cast<const ulonglong2*>(&swf[c * 8]);
                ulonglong2 wA = wp[0], wB = wp[1];
                unsigned long long lc = pk2(lg[c], lg[c]);
                o01 = ffma2(lc, wA.x, o01);
                o23 = ffma2(lc, wA.y, o23);
                o45 = ffma2(lc, wB.x, o45);
                o67 = ffma2(lc, wB.y, o67);
            }
            float out[8];
            upk2(o01, out[0], out[1]); upk2(o23, out[2], out[3]);
            upk2(o45, out[4], out[5]); upk2(o67, out[6], out[7]);

            if (logits_out) {
                float4* lo = reinterpret_cast<float4*>(logits_out + gi);
                lo[0] = make_float4(out[0], out[1], out[2], out[3]);
                lo[1] = make_float4(out[4], out[5], out[6], out[7]);
            } else {
                float m = out[0];
#pragma unroll
                for (int c = 1; c < 8; c++) m = fmaxf(m, out[c]);
                float e[8], s = 0.f;
#pragma unroll
                for (int c = 0; c < 8; c++) { e[c] = __expf(out[c] - m); s += e[c]; }
                float inv = 1.f / s;
                uint4 qv;
                qv.x = h2pack(e[0] * inv, e[1] * inv);
                qv.y = h2pack(e[2] * inv, e[3] * inv);
                qv.z = h2pack(e[4] * inv, e[5] * inv);
                qv.w = h2pack(e[6] * inv, e[7] * inv);
                reinterpret_cast<uint4*>(qout)[gi >> 3] = qv;
            }
        }

        if (p < ROWS_PER / RPASS - 1) cpa_wait0();
        __syncthreads();
    }
}

// ============================================================
extern "C" void kernel_launch(void* const* d_in, const int* in_sizes, int n_in,
                              void* d_out, int out_size) {
    const float* x  = (const float*)d_in[0];
    const float* kw = (const float*)d_in[1];
    const float* ws = (const float*)d_in[2];
    const float* bs = (const float*)d_in[3];

    __half *qA, *qB;
    float* uu;
    cudaGetSymbolAddress((void**)&qA, g_qA);
    cudaGetSymbolAddress((void**)&qB, g_qB);
    cudaGetSymbolAddress((void**)&uu, g_u);

    k_init<<<(NPIX + 255) / 256, 256>>>(x, qA, uu);

    dim3 grid(Wn / TILE_X, Hn / ROWS_PER, Bn);   // (3, 24, 32) = 2304 CTAs
    __half* src = qA;
    __half* dst = qB;
    for (int it = 0; it < 5; it++) {
        float* lo = (it == 4) ? (float*)d_out : nullptr;
        k_iter<<<grid, 128>>>(src, uu, kw, ws, bs, dst, lo);
        __half* t = src; src = dst; dst = t;
    }
}